// round 14
// baseline (speedup 1.0000x reference)
#include <cuda_runtime.h>
#include <cuda_fp16.h>
#include <stdint.h>

#define NROWS  16384
#define NCODES 8192
#define KDIM   256
#define ZELEMS (NROWS * KDIM)
#define B1 16.0f
#define NCHUNK 8
#define MT_PER_CHUNK 16            // 16 m-tiles (2048 rows) per chunk

typedef __half fp16;

__device__ float g_logits[(size_t)NROWS * NCODES];
__device__ fp16  g_Whi[(size_t)NROWS * NCODES];
__device__ fp16  g_Ahi[ZELEMS], g_Alo[ZELEMS];
__device__ fp16  g_Bhi[NCODES * KDIM], g_Blo[NCODES * KDIM];
__device__ fp16  g_CThi[(size_t)KDIM * NCODES], g_CTlo[(size_t)KDIM * NCODES];
__device__ float g_kl[NROWS];
__device__ float g_sse[128];

// ---------------- PTX helpers ----------------------------------------------
__device__ __forceinline__ uint32_t smem_u32(const void* p) {
    uint32_t a;
    asm("{ .reg .u64 t; cvta.to.shared.u64 t, %1; cvt.u32.u64 %0, t; }" : "=r"(a) : "l"(p));
    return a;
}
__device__ __forceinline__ void cp16(uint32_t dst, const void* src) {
    asm volatile("cp.async.cg.shared.global [%0], [%1], 16;\n" :: "r"(dst), "l"(src));
}
__device__ __forceinline__ void cp_commit() { asm volatile("cp.async.commit_group;\n" ::: "memory"); }
template<int N> __device__ __forceinline__ void cp_wait() {
    asm volatile("cp.async.wait_group %0;\n" :: "n"(N) : "memory");
}
__device__ __forceinline__ void ldsm4(uint32_t* r, uint32_t addr) {
    asm volatile("ldmatrix.sync.aligned.m8n8.x4.shared.b16 {%0,%1,%2,%3}, [%4];"
        : "=r"(r[0]), "=r"(r[1]), "=r"(r[2]), "=r"(r[3]) : "r"(addr));
}
__device__ __forceinline__ void mma16816(float* c, const uint32_t* a, const uint32_t* b) {
    asm volatile("mma.sync.aligned.m16n8k16.row.col.f32.f16.f16.f32 "
        "{%0,%1,%2,%3}, {%4,%5,%6,%7}, {%8,%9}, {%0,%1,%2,%3};"
        : "+f"(c[0]), "+f"(c[1]), "+f"(c[2]), "+f"(c[3])
        : "r"(a[0]), "r"(a[1]), "r"(a[2]), "r"(a[3]), "r"(b[0]), "r"(b[1]));
}

// ---------------- threefry2x32 key (0,42); G' = exp(g-24) -------------------
__device__ __forceinline__ uint2 tf2x32(uint32_t x0, uint32_t x1) {
    const uint32_t ks1 = 42u, ks2 = 0x1BD11BDAu ^ 42u;
    x1 += ks1;
#define TFR(r) { x0 += x1; x1 = (x1 << (r)) | (x1 >> (32 - (r))); x1 ^= x0; }
    TFR(13) TFR(15) TFR(26) TFR(6)
    x0 += ks1; x1 += ks2 + 1u;
    TFR(17) TFR(29) TFR(16) TFR(24)
    x0 += ks2; x1 += 2u;
    TFR(13) TFR(15) TFR(26) TFR(6)
    x1 += ks1 + 3u;
    TFR(17) TFR(29) TFR(16) TFR(24)
    x0 += ks1; x1 += ks2 + 4u;
    TFR(13) TFR(15) TFR(26) TFR(6)
    x0 += ks2; x1 += 5u;
#undef TFR
    return make_uint2(x0, x1);
}
__device__ __forceinline__ float gprime_at(uint32_t j) {
    uint2 t = tf2x32(0u, j);
    uint32_t bits = t.x ^ t.y;
    float f = __uint_as_float((bits >> 9) | 0x3f800000u) - 1.0f;
    f = fmaxf(f, 1.17549435e-38f);
    float tt = f - 1.0f;
    float inner;
    if (tt > -0.00390625f)
        inner = tt * (1.0f + tt * (-0.5f + tt * 0.33333333f));
    else
        inner = __logf(f);
    return __fdividef(3.7751345e-11f, -inner);
}

// ---------------- reductions (256 threads) ----------------------------------
__device__ __forceinline__ float blockSum(float v, float* sc) {
    int lane = threadIdx.x & 31, w = threadIdx.x >> 5;
#pragma unroll
    for (int o = 16; o; o >>= 1) v += __shfl_xor_sync(0xffffffffu, v, o);
    if (lane == 0) sc[w] = v;
    __syncthreads();
    if (w == 0) {
        float x = (lane < 8) ? sc[lane] : 0.f;
#pragma unroll
        for (int o = 4; o; o >>= 1) x += __shfl_xor_sync(0xffffffffu, x, o);
        if (lane == 0) sc[0] = x;
    }
    __syncthreads();
    float r = sc[0];
    __syncthreads();
    return r;
}
__device__ __forceinline__ void blockArgmax(float& v, int& idx, float* scv, int* sci) {
    int lane = threadIdx.x & 31, w = threadIdx.x >> 5;
#pragma unroll
    for (int o = 16; o; o >>= 1) {
        float ov = __shfl_xor_sync(0xffffffffu, v, o);
        int   oi = __shfl_xor_sync(0xffffffffu, idx, o);
        if (ov > v || (ov == v && oi < idx)) { v = ov; idx = oi; }
    }
    if (lane == 0) { scv[w] = v; sci[w] = idx; }
    __syncthreads();
    if (w == 0) {
        float x = (lane < 8) ? scv[lane] : -3.4e38f;
        int   i = (lane < 8) ? sci[lane] : 0x7fffffff;
#pragma unroll
        for (int o = 4; o; o >>= 1) {
            float ov = __shfl_xor_sync(0xffffffffu, x, o);
            int   oi = __shfl_xor_sync(0xffffffffu, i, o);
            if (ov > x || (ov == x && oi < i)) { x = ov; i = oi; }
        }
        if (lane == 0) { scv[0] = x; sci[0] = i; }
    }
    __syncthreads();
    v = scv[0]; idx = sci[0];
    __syncthreads();
}

// ---------------- split kernels ---------------------------------------------
__global__ __launch_bounds__(256) void split_z(const float* __restrict__ z) {
    int i = blockIdx.x * 256 + threadIdx.x;
    float x = z[i];
    fp16 h = __float2half_rn(x);
    g_Ahi[i] = h;
    g_Alo[i] = __float2half_rn(x - __half2float(h));
}
__global__ __launch_bounds__(256) void split_cb(const float* __restrict__ cb) {
    __shared__ fp16 th[64][65], tl[64][65];
    int bc = blockIdx.x * 64, bd = blockIdx.y * 64;
    int t = threadIdx.x;
#pragma unroll 4
    for (int cc = 0; cc < 16; cc++) {
        int c = (t >> 6) * 16 + cc;
        int d = t & 63;
        size_t gi = (size_t)(bc + c) * KDIM + bd + d;
        float x = cb[gi];
        fp16 h = __float2half_rn(x);
        fp16 l = __float2half_rn(x - __half2float(h));
        g_Bhi[gi] = h; g_Blo[gi] = l;
        th[c][d] = h; tl[c][d] = l;
    }
    __syncthreads();
#pragma unroll 4
    for (int dd = 0; dd < 16; dd++) {
        int d = (t >> 6) * 16 + dd;
        int c = t & 63;
        size_t gi = (size_t)(bd + d) * NCODES + bc + c;
        g_CThi[gi] = th[c][d];
        g_CTlo[gi] = tl[c][d];
    }
}

// ---------------- gemm1 (R13 2-stage), m-tile offset ------------------------
#define ASTR 40
#define TILE_B (128 * ASTR * 2)

__global__ __launch_bounds__(128) void gemm1(int mt0) {
    __shared__ fp16 sA[2][128 * ASTR];
    __shared__ fp16 sB[2][128 * ASTR];

    int tid = threadIdx.x, lane = tid & 31, wid = tid >> 5;
    int wm = wid >> 1, wn = wid & 1;
    int m0 = (mt0 + blockIdx.y) * 128, n0 = blockIdx.x * 128;

    const int NIT = 24;
    const fp16* At[3] = { g_Ahi, g_Alo, g_Ahi };
    const fp16* Bt[3] = { g_Bhi, g_Bhi, g_Blo };

    uint32_t sA0 = smem_u32(&sA[0][0]);
    uint32_t sB0 = smem_u32(&sB[0][0]);

    float acc[4][8][4] = {};

    auto load_stage = [&](int it, int s) {
        int term = it >> 3, k0 = (it & 7) * 32;
        const fp16* A = At[term];
        const fp16* B = Bt[term];
        uint32_t da = sA0 + s * TILE_B;
        uint32_t db = sB0 + s * TILE_B;
#pragma unroll
        for (int i = 0; i < 4; i++) {
            int idx = tid + i * 128;
            int row = idx >> 2, ch = idx & 3;
            cp16(da + row * 80 + ch * 16, A + (size_t)(m0 + row) * KDIM + k0 + ch * 8);
            cp16(db + row * 80 + ch * 16, B + (size_t)(n0 + row) * KDIM + k0 + ch * 8);
        }
        cp_commit();
    };

    load_stage(0, 0);
    for (int it = 0; it < NIT; it++) {
        int s = it & 1;
        cp_wait<0>();
        __syncthreads();
        if (it + 1 < NIT) load_stage(it + 1, s ^ 1);
        uint32_t da = sA0 + s * TILE_B;
        uint32_t db = sB0 + s * TILE_B;
#pragma unroll
        for (int ks = 0; ks < 32; ks += 16) {
            uint32_t af[4][4], bq[4][4];
#pragma unroll
            for (int mt = 0; mt < 4; mt++)
                ldsm4(af[mt], da + (uint32_t)((wm * 64 + mt * 16 + (lane & 15)) * 80
                                              + (ks + ((lane >> 4) << 3)) * 2));
#pragma unroll
            for (int np = 0; np < 4; np++)
                ldsm4(bq[np], db + (uint32_t)((wn * 64 + np * 16 + (lane & 7) + ((lane >> 4) << 3)) * 80
                                              + (ks + (((lane >> 3) & 1) << 3)) * 2));
#pragma unroll
            for (int mt = 0; mt < 4; mt++)
#pragma unroll
                for (int nt = 0; nt < 8; nt++)
                    mma16816(acc[mt][nt], af[mt], &bq[nt >> 1][(nt & 1) * 2]);
        }
    }

    int rbase = m0 + wm * 64 + (lane >> 2);
    int cbase = n0 + wn * 64 + (lane & 3) * 2;
#pragma unroll
    for (int mt = 0; mt < 4; mt++)
#pragma unroll
        for (int nt = 0; nt < 8; nt++) {
            int r0 = rbase + mt * 16, c0 = cbase + nt * 8;
            *(float2*)(g_logits + (size_t)r0 * NCODES + c0)       = make_float2(acc[mt][nt][0], acc[mt][nt][1]);
            *(float2*)(g_logits + (size_t)(r0 + 8) * NCODES + c0) = make_float2(acc[mt][nt][2], acc[mt][nt][3]);
        }
}

// ---------------- rowops (R13), row offset ----------------------------------
__global__ __launch_bounds__(256) void rowops(float* __restrict__ outCodes, int r0off) {
    __shared__ float st[NCODES];
    __shared__ float scv[8];
    __shared__ int   sci[8];

    int r = r0off + blockIdx.x;
    const float* L = g_logits + (size_t)r * NCODES;

    float mx = -3.4e38f; int ai = 0;
    float se = 0.f, sel = 0.f, sy = 0.f;
    uint32_t jb = (uint32_t)r * (uint32_t)NCODES;
    for (int c = threadIdx.x; c < NCODES; c += 256) {
        float l = L[c];
        float e = __expf(l - B1);
        float t = e * gprime_at(jb + (uint32_t)c);
        st[c] = t;
        se += e; sel += e * l; sy += t;
        if (l > mx) { mx = l; ai = c; }
    }
    __syncthreads();

    blockArgmax(mx, ai, scv, sci);
    float SE  = blockSum(se, scv);
    float SEl = blockSum(sel, scv);
    float SY  = blockSum(sy, scv);

    float inv = 1.0f / SY;
    fp16* wh = g_Whi + (size_t)r * NCODES;
    for (int c = threadIdx.x; c < NCODES; c += 256) {
        wh[c] = __float2half_rn(st[c] * inv);
    }
    if (threadIdx.x == 0) {
        g_kl[r] = SEl / SE - (B1 + __logf(SE)) + 9.0109131f;   // + ln 8192
        outCodes[r] = (float)ai;
    }
}

// ---------------- gemm2 (R13 2-term), whole ---------------------------------
#define G2_STG 51200u
#define G2_DYN (2 * G2_STG)

__global__ __launch_bounds__(256) void gemm2(const float* __restrict__ Z,
                                             float* __restrict__ Out) {
    extern __shared__ __align__(16) char dyn2[];
    __shared__ float ssum[8];
    uint32_t sm = smem_u32(dyn2);
    int tid = threadIdx.x, lane = tid & 31, wid = tid >> 5;
    int wm = wid >> 2, wn = wid & 3;
    int m0 = blockIdx.x * 128;

    float acc[4][8][4] = {};

    auto load_stage = [&](int it, int s) {
        int k0 = it * 32;
        uint32_t b = sm + s * G2_STG;
#pragma unroll
        for (int i = 0; i < 10; i++) {
            int idx = tid + i * 256;
            if (idx < 512) {
                int row = idx >> 2, ch = idx & 3;
                cp16(b + row * 80 + ch * 16, g_Whi + (size_t)(m0 + row) * NCODES + k0 + ch * 8);
            } else if (idx < 1536) {
                int j = idx - 512; int row = j >> 2, ch = j & 3;
                cp16(b + 10240 + row * 80 + ch * 16, g_CThi + (size_t)row * NCODES + k0 + ch * 8);
            } else {
                int j = idx - 1536; int row = j >> 2, ch = j & 3;
                cp16(b + 30720 + row * 80 + ch * 16, g_CTlo + (size_t)row * NCODES + k0 + ch * 8);
            }
        }
        cp_commit();
    };

    load_stage(0, 0);
    for (int it = 0; it < 256; it++) {
        int s = it & 1;
        cp_wait<0>();
        __syncthreads();
        if (it + 1 < 256) load_stage(it + 1, s ^ 1);
        uint32_t bh  = sm + s * G2_STG;
        uint32_t chh = bh + 10240;
        uint32_t cll = bh + 30720;
#pragma unroll
        for (int ks = 0; ks < 32; ks += 16) {
            uint32_t aoff = (uint32_t)((wm * 64 + (lane & 15)) * 80 + (ks + ((lane >> 4) << 3)) * 2);
            uint32_t boff = (uint32_t)((wn * 64 + (lane & 7) + ((lane >> 4) << 3)) * 80
                                       + (ks + (((lane >> 3) & 1) << 3)) * 2);
            uint32_t ah[4][4], bq[4][4];
#pragma unroll
            for (int mt = 0; mt < 4; mt++)
                ldsm4(ah[mt], bh + aoff + mt * 16 * 80);
#pragma unroll
            for (int np = 0; np < 4; np++)
                ldsm4(bq[np], chh + boff + np * 16 * 80);
#pragma unroll
            for (int mt = 0; mt < 4; mt++)
#pragma unroll
                for (int nt = 0; nt < 8; nt++)
                    mma16816(acc[mt][nt], ah[mt], &bq[nt >> 1][(nt & 1) * 2]);
#pragma unroll
            for (int np = 0; np < 4; np++)
                ldsm4(bq[np], cll + boff + np * 16 * 80);
#pragma unroll
            for (int mt = 0; mt < 4; mt++)
#pragma unroll
                for (int nt = 0; nt < 8; nt++)
                    mma16816(acc[mt][nt], ah[mt], &bq[nt >> 1][(nt & 1) * 2]);
        }
    }

    int rbase = m0 + wm * 64 + (lane >> 2);
    int cbase = wn * 64 + (lane & 3) * 2;
    float sse = 0.f;
#pragma unroll
    for (int mt = 0; mt < 4; mt++)
#pragma unroll
        for (int nt = 0; nt < 8; nt++) {
            int r0 = rbase + mt * 16, c0 = cbase + nt * 8;
#pragma unroll
            for (int h = 0; h < 2; h++) {
                size_t o = (size_t)(r0 + h * 8) * KDIM + c0;
                float2 zv = *(const float2*)(Z + o);
                float dx = acc[mt][nt][h * 2]     - zv.x;
                float dy = acc[mt][nt][h * 2 + 1] - zv.y;
                sse += dx * dx + dy * dy;
                *(float2*)(Out + o) = make_float2(zv.x + dx, zv.y + dy);
            }
        }
#pragma unroll
    for (int o = 16; o; o >>= 1) sse += __shfl_xor_sync(0xffffffffu, sse, o);
    if (lane == 0) ssum[wid] = sse;
    __syncthreads();
    if (tid == 0) {
        float t = 0.f;
#pragma unroll
        for (int i = 0; i < 8; i++) t += ssum[i];
        g_sse[blockIdx.x] = t;
    }
}

// ---------------- finalize --------------------------------------------------
__global__ __launch_bounds__(256) void finalize(float* __restrict__ outLoss) {
    __shared__ float sc[8];
    float k = 0.f;
    for (int i = threadIdx.x; i < NROWS; i += 256) k += g_kl[i];
    float K = blockSum(k, sc);
    float e = (threadIdx.x < 128) ? g_sse[threadIdx.x] : 0.f;
    float E = blockSum(e, sc);
    if (threadIdx.x == 0)
        outLoss[0] = 0.25f * (E / (float)ZELEMS) + 0.01f * (K / (float)NROWS);
}

// ---------------- launch: gemm1 || rowops pipeline, whole gemm2 -------------
extern "C" void kernel_launch(void* const* d_in, const int* in_sizes, int n_in,
                              void* d_out, int out_size) {
    const float* z  = (const float*)d_in[0];
    const float* cb = (const float*)d_in[1];
    float* out = (float*)d_out;
    float* outZ     = out;
    float* outLoss  = out + ZELEMS;
    float* outCodes = out + ZELEMS + 1;

    static cudaStream_t s1 = nullptr;
    static cudaEvent_t eg[NCHUNK], er;
    if (!s1) {
        cudaStreamCreateWithFlags(&s1, cudaStreamNonBlocking);
        for (int c = 0; c < NCHUNK; c++)
            cudaEventCreateWithFlags(&eg[c], cudaEventDisableTiming);
        cudaEventCreateWithFlags(&er, cudaEventDisableTiming);
        cudaFuncSetAttribute(gemm2, cudaFuncAttributeMaxDynamicSharedMemorySize, G2_DYN);
    }

    split_z<<<ZELEMS / 256, 256>>>(z);
    dim3 gs(NCODES / 64, KDIM / 64);
    split_cb<<<gs, 256>>>(cb);

    for (int c = 0; c < NCHUNK; c++) {
        dim3 g1(NCODES / 128, MT_PER_CHUNK);
        gemm1<<<g1, 128>>>(c * MT_PER_CHUNK);
        cudaEventRecord(eg[c], 0);
        cudaStreamWaitEvent(s1, eg[c], 0);
        rowops<<<MT_PER_CHUNK * 128, 256, 0, s1>>>(outCodes, c * MT_PER_CHUNK * 128);
    }
    cudaEventRecord(er, s1);
    cudaStreamWaitEvent(0, er, 0);

    gemm2<<<NROWS / 128, 256, G2_DYN>>>(z, outZ);

    finalize<<<1, 256>>>(outLoss);
}

// round 15
// speedup vs baseline: 1.0565x; 1.0565x over previous
#include <cuda_runtime.h>
#include <cuda_fp16.h>
#include <stdint.h>

#define NROWS  16384
#define NCODES 8192
#define KDIM   256
#define ZELEMS (NROWS * KDIM)
#define B1 16.0f

typedef __half fp16;

__device__ float g_logits[(size_t)NROWS * NCODES];
__device__ fp16  g_Whi[(size_t)NROWS * NCODES];
__device__ fp16  g_Ahi[ZELEMS], g_Alo[ZELEMS];
__device__ fp16  g_Bhi[NCODES * KDIM], g_Blo[NCODES * KDIM];
__device__ fp16  g_CThi[(size_t)KDIM * NCODES], g_CTlo[(size_t)KDIM * NCODES];
__device__ float g_kl[NROWS];
__device__ float g_sse[256];

// ---------------- PTX helpers ----------------------------------------------
__device__ __forceinline__ uint32_t smem_u32(const void* p) {
    uint32_t a;
    asm("{ .reg .u64 t; cvta.to.shared.u64 t, %1; cvt.u32.u64 %0, t; }" : "=r"(a) : "l"(p));
    return a;
}
__device__ __forceinline__ void cp16(uint32_t dst, const void* src) {
    asm volatile("cp.async.cg.shared.global [%0], [%1], 16;\n" :: "r"(dst), "l"(src));
}
__device__ __forceinline__ void cp_commit() { asm volatile("cp.async.commit_group;\n" ::: "memory"); }
template<int N> __device__ __forceinline__ void cp_wait() {
    asm volatile("cp.async.wait_group %0;\n" :: "n"(N) : "memory");
}
__device__ __forceinline__ void ldsm4(uint32_t* r, uint32_t addr) {
    asm volatile("ldmatrix.sync.aligned.m8n8.x4.shared.b16 {%0,%1,%2,%3}, [%4];"
        : "=r"(r[0]), "=r"(r[1]), "=r"(r[2]), "=r"(r[3]) : "r"(addr));
}
__device__ __forceinline__ void mma16816(float* c, const uint32_t* a, const uint32_t* b) {
    asm volatile("mma.sync.aligned.m16n8k16.row.col.f32.f16.f16.f32 "
        "{%0,%1,%2,%3}, {%4,%5,%6,%7}, {%8,%9}, {%0,%1,%2,%3};"
        : "+f"(c[0]), "+f"(c[1]), "+f"(c[2]), "+f"(c[3])
        : "r"(a[0]), "r"(a[1]), "r"(a[2]), "r"(a[3]), "r"(b[0]), "r"(b[1]));
}

// ---------------- threefry2x32 key (0,42); G' = exp(g-24) -------------------
__device__ __forceinline__ uint2 tf2x32(uint32_t x0, uint32_t x1) {
    const uint32_t ks1 = 42u, ks2 = 0x1BD11BDAu ^ 42u;
    x1 += ks1;
#define TFR(r) { x0 += x1; x1 = (x1 << (r)) | (x1 >> (32 - (r))); x1 ^= x0; }
    TFR(13) TFR(15) TFR(26) TFR(6)
    x0 += ks1; x1 += ks2 + 1u;
    TFR(17) TFR(29) TFR(16) TFR(24)
    x0 += ks2; x1 += 2u;
    TFR(13) TFR(15) TFR(26) TFR(6)
    x1 += ks1 + 3u;
    TFR(17) TFR(29) TFR(16) TFR(24)
    x0 += ks1; x1 += ks2 + 4u;
    TFR(13) TFR(15) TFR(26) TFR(6)
    x0 += ks2; x1 += 5u;
#undef TFR
    return make_uint2(x0, x1);
}
__device__ __forceinline__ float gprime_at(uint32_t j) {
    uint2 t = tf2x32(0u, j);
    uint32_t bits = t.x ^ t.y;
    float f = __uint_as_float((bits >> 9) | 0x3f800000u) - 1.0f;
    f = fmaxf(f, 1.17549435e-38f);
    float tt = f - 1.0f;
    float inner;
    if (tt > -0.00390625f)
        inner = tt * (1.0f + tt * (-0.5f + tt * 0.33333333f));
    else
        inner = __logf(f);
    return __fdividef(3.7751345e-11f, -inner);
}

// ---------------- reductions (256 threads) ----------------------------------
__device__ __forceinline__ float blockSum(float v, float* sc) {
    int lane = threadIdx.x & 31, w = threadIdx.x >> 5;
#pragma unroll
    for (int o = 16; o; o >>= 1) v += __shfl_xor_sync(0xffffffffu, v, o);
    if (lane == 0) sc[w] = v;
    __syncthreads();
    if (w == 0) {
        float x = (lane < 8) ? sc[lane] : 0.f;
#pragma unroll
        for (int o = 4; o; o >>= 1) x += __shfl_xor_sync(0xffffffffu, x, o);
        if (lane == 0) sc[0] = x;
    }
    __syncthreads();
    float r = sc[0];
    __syncthreads();
    return r;
}
__device__ __forceinline__ void blockArgmax(float& v, int& idx, float* scv, int* sci) {
    int lane = threadIdx.x & 31, w = threadIdx.x >> 5;
#pragma unroll
    for (int o = 16; o; o >>= 1) {
        float ov = __shfl_xor_sync(0xffffffffu, v, o);
        int   oi = __shfl_xor_sync(0xffffffffu, idx, o);
        if (ov > v || (ov == v && oi < idx)) { v = ov; idx = oi; }
    }
    if (lane == 0) { scv[w] = v; sci[w] = idx; }
    __syncthreads();
    if (w == 0) {
        float x = (lane < 8) ? scv[lane] : -3.4e38f;
        int   i = (lane < 8) ? sci[lane] : 0x7fffffff;
#pragma unroll
        for (int o = 4; o; o >>= 1) {
            float ov = __shfl_xor_sync(0xffffffffu, x, o);
            int   oi = __shfl_xor_sync(0xffffffffu, i, o);
            if (ov > x || (ov == x && oi < i)) { x = ov; i = oi; }
        }
        if (lane == 0) { scv[0] = x; sci[0] = i; }
    }
    __syncthreads();
    v = scv[0]; idx = sci[0];
    __syncthreads();
}

// ---------------- split kernels ---------------------------------------------
__global__ __launch_bounds__(256) void split_z(const float* __restrict__ z) {
    int i = blockIdx.x * 256 + threadIdx.x;
    float x = z[i];
    fp16 h = __float2half_rn(x);
    g_Ahi[i] = h;
    g_Alo[i] = __float2half_rn(x - __half2float(h));
}
__global__ __launch_bounds__(256) void split_cb(const float* __restrict__ cb) {
    __shared__ fp16 th[64][65], tl[64][65];
    int bc = blockIdx.x * 64, bd = blockIdx.y * 64;
    int t = threadIdx.x;
#pragma unroll 4
    for (int cc = 0; cc < 16; cc++) {
        int c = (t >> 6) * 16 + cc;
        int d = t & 63;
        size_t gi = (size_t)(bc + c) * KDIM + bd + d;
        float x = cb[gi];
        fp16 h = __float2half_rn(x);
        fp16 l = __float2half_rn(x - __half2float(h));
        g_Bhi[gi] = h; g_Blo[gi] = l;
        th[c][d] = h; tl[c][d] = l;
    }
    __syncthreads();
#pragma unroll 4
    for (int dd = 0; dd < 16; dd++) {
        int d = (t >> 6) * 16 + dd;
        int c = t & 63;
        size_t gi = (size_t)(bd + d) * NCODES + bc + c;
        g_CThi[gi] = th[c][d];
        g_CTlo[gi] = tl[c][d];
    }
}

// ---------------- gemm1 (R13-verbatim): logits, 3-term ----------------------
#define ASTR 40
#define TILE_B (128 * ASTR * 2)

__global__ __launch_bounds__(128) void gemm1() {
    __shared__ fp16 sA[2][128 * ASTR];
    __shared__ fp16 sB[2][128 * ASTR];

    int tid = threadIdx.x, lane = tid & 31, wid = tid >> 5;
    int wm = wid >> 1, wn = wid & 1;
    int m0 = blockIdx.y * 128, n0 = blockIdx.x * 128;

    const int NIT = 24;
    const fp16* At[3] = { g_Ahi, g_Alo, g_Ahi };
    const fp16* Bt[3] = { g_Bhi, g_Bhi, g_Blo };

    uint32_t sA0 = smem_u32(&sA[0][0]);
    uint32_t sB0 = smem_u32(&sB[0][0]);

    float acc[4][8][4] = {};

    auto load_stage = [&](int it, int s) {
        int term = it >> 3, k0 = (it & 7) * 32;
        const fp16* A = At[term];
        const fp16* B = Bt[term];
        uint32_t da = sA0 + s * TILE_B;
        uint32_t db = sB0 + s * TILE_B;
#pragma unroll
        for (int i = 0; i < 4; i++) {
            int idx = tid + i * 128;
            int row = idx >> 2, ch = idx & 3;
            cp16(da + row * 80 + ch * 16, A + (size_t)(m0 + row) * KDIM + k0 + ch * 8);
            cp16(db + row * 80 + ch * 16, B + (size_t)(n0 + row) * KDIM + k0 + ch * 8);
        }
        cp_commit();
    };

    load_stage(0, 0);
    for (int it = 0; it < NIT; it++) {
        int s = it & 1;
        cp_wait<0>();
        __syncthreads();
        if (it + 1 < NIT) load_stage(it + 1, s ^ 1);
        uint32_t da = sA0 + s * TILE_B;
        uint32_t db = sB0 + s * TILE_B;
#pragma unroll
        for (int ks = 0; ks < 32; ks += 16) {
            uint32_t af[4][4], bq[4][4];
#pragma unroll
            for (int mt = 0; mt < 4; mt++)
                ldsm4(af[mt], da + (uint32_t)((wm * 64 + mt * 16 + (lane & 15)) * 80
                                              + (ks + ((lane >> 4) << 3)) * 2));
#pragma unroll
            for (int np = 0; np < 4; np++)
                ldsm4(bq[np], db + (uint32_t)((wn * 64 + np * 16 + (lane & 7) + ((lane >> 4) << 3)) * 80
                                              + (ks + (((lane >> 3) & 1) << 3)) * 2));
#pragma unroll
            for (int mt = 0; mt < 4; mt++)
#pragma unroll
                for (int nt = 0; nt < 8; nt++)
                    mma16816(acc[mt][nt], af[mt], &bq[nt >> 1][(nt & 1) * 2]);
        }
    }

    int rbase = m0 + wm * 64 + (lane >> 2);
    int cbase = n0 + wn * 64 + (lane & 3) * 2;
#pragma unroll
    for (int mt = 0; mt < 4; mt++)
#pragma unroll
        for (int nt = 0; nt < 8; nt++) {
            int r0 = rbase + mt * 16, c0 = cbase + nt * 8;
            *(float2*)(g_logits + (size_t)r0 * NCODES + c0)       = make_float2(acc[mt][nt][0], acc[mt][nt][1]);
            *(float2*)(g_logits + (size_t)(r0 + 8) * NCODES + c0) = make_float2(acc[mt][nt][2], acc[mt][nt][3]);
        }
}

// ---------------- rowops (R13-verbatim) -------------------------------------
__global__ __launch_bounds__(256) void rowops(float* __restrict__ outCodes) {
    __shared__ float st[NCODES];
    __shared__ float scv[8];
    __shared__ int   sci[8];

    int r = blockIdx.x;
    const float* L = g_logits + (size_t)r * NCODES;

    float mx = -3.4e38f; int ai = 0;
    float se = 0.f, sel = 0.f, sy = 0.f;
    uint32_t jb = (uint32_t)r * (uint32_t)NCODES;
    for (int c = threadIdx.x; c < NCODES; c += 256) {
        float l = L[c];
        float e = __expf(l - B1);
        float t = e * gprime_at(jb + (uint32_t)c);
        st[c] = t;
        se += e; sel += e * l; sy += t;
        if (l > mx) { mx = l; ai = c; }
    }
    __syncthreads();

    blockArgmax(mx, ai, scv, sci);
    float SE  = blockSum(se, scv);
    float SEl = blockSum(sel, scv);
    float SY  = blockSum(sy, scv);

    float inv = 1.0f / SY;
    fp16* wh = g_Whi + (size_t)r * NCODES;
    for (int c = threadIdx.x; c < NCODES; c += 256) {
        wh[c] = __float2half_rn(st[c] * inv);
    }
    if (threadIdx.x == 0) {
        g_kl[r] = SEl / SE - (B1 + __logf(SE)) + 9.0109131f;   // + ln 8192
        outCodes[r] = (float)ai;
    }
}

// ---------------- gemm2: z_q 128x128 tile, 2-term, 2 CTAs/SM ----------------
// grid (2, 128): bx = d-tile (KDIM half), by = m-tile. 128 threads, 4 warps.
// Stage: Whi @0 (10240), CThi @10240 (10240), CTlo @20480 (10240) = 30720 B.
#define G2_STG 30720u
#define G2_DYN (2 * G2_STG)

__global__ __launch_bounds__(128) void gemm2(const float* __restrict__ Z,
                                             float* __restrict__ Out) {
    extern __shared__ __align__(16) char dyn2[];
    __shared__ float ssum[4];
    uint32_t sm = smem_u32(dyn2);
    int tid = threadIdx.x, lane = tid & 31, wid = tid >> 5;
    int wm = wid >> 1, wn = wid & 1;
    int m0 = blockIdx.y * 128;
    int n0 = blockIdx.x * 128;          // over KDIM

    float acc[4][8][4] = {};

    auto load_stage = [&](int it, int s) {
        int k0 = it * 32;
        uint32_t b = sm + s * G2_STG;
#pragma unroll
        for (int i = 0; i < 12; i++) {
            int idx = tid + i * 128;               // 0..1535
            if (idx < 512) {
                int row = idx >> 2, ch = idx & 3;
                cp16(b + row * 80 + ch * 16, g_Whi + (size_t)(m0 + row) * NCODES + k0 + ch * 8);
            } else if (idx < 1024) {
                int j = idx - 512; int row = j >> 2, ch = j & 3;
                cp16(b + 10240 + row * 80 + ch * 16,
                     g_CThi + (size_t)(n0 + row) * NCODES + k0 + ch * 8);
            } else {
                int j = idx - 1024; int row = j >> 2, ch = j & 3;
                cp16(b + 20480 + row * 80 + ch * 16,
                     g_CTlo + (size_t)(n0 + row) * NCODES + k0 + ch * 8);
            }
        }
        cp_commit();
    };

    load_stage(0, 0);
    for (int it = 0; it < 256; it++) {
        int s = it & 1;
        cp_wait<0>();
        __syncthreads();
        if (it + 1 < 256) load_stage(it + 1, s ^ 1);
        uint32_t bh  = sm + s * G2_STG;
        uint32_t chh = bh + 10240;
        uint32_t cll = bh + 20480;
#pragma unroll
        for (int ks = 0; ks < 32; ks += 16) {
            uint32_t aoff = (uint32_t)((wm * 64 + (lane & 15)) * 80 + (ks + ((lane >> 4) << 3)) * 2);
            uint32_t boff = (uint32_t)((wn * 64 + (lane & 7) + ((lane >> 4) << 3)) * 80
                                       + (ks + (((lane >> 3) & 1) << 3)) * 2);
            uint32_t ah[4][4], bq[4][4];
#pragma unroll
            for (int mt = 0; mt < 4; mt++)
                ldsm4(ah[mt], bh + aoff + mt * 16 * 80);
#pragma unroll
            for (int np = 0; np < 4; np++)
                ldsm4(bq[np], chh + boff + np * 16 * 80);
#pragma unroll
            for (int mt = 0; mt < 4; mt++)
#pragma unroll
                for (int nt = 0; nt < 8; nt++)
                    mma16816(acc[mt][nt], ah[mt], &bq[nt >> 1][(nt & 1) * 2]);
#pragma unroll
            for (int np = 0; np < 4; np++)
                ldsm4(bq[np], cll + boff + np * 16 * 80);
#pragma unroll
            for (int mt = 0; mt < 4; mt++)
#pragma unroll
                for (int nt = 0; nt < 8; nt++)
                    mma16816(acc[mt][nt], ah[mt], &bq[nt >> 1][(nt & 1) * 2]);
        }
    }

    int rbase = m0 + wm * 64 + (lane >> 2);
    int cbase = n0 + wn * 64 + (lane & 3) * 2;
    float sse = 0.f;
#pragma unroll
    for (int mt = 0; mt < 4; mt++)
#pragma unroll
        for (int nt = 0; nt < 8; nt++) {
            int r0 = rbase + mt * 16, c0 = cbase + nt * 8;
#pragma unroll
            for (int h = 0; h < 2; h++) {
                size_t o = (size_t)(r0 + h * 8) * KDIM + c0;
                float2 zv = *(const float2*)(Z + o);
                float dx = acc[mt][nt][h * 2]     - zv.x;
                float dy = acc[mt][nt][h * 2 + 1] - zv.y;
                sse += dx * dx + dy * dy;
                *(float2*)(Out + o) = make_float2(zv.x + dx, zv.y + dy);
            }
        }
#pragma unroll
    for (int o = 16; o; o >>= 1) sse += __shfl_xor_sync(0xffffffffu, sse, o);
    if (lane == 0) ssum[wid] = sse;
    __syncthreads();
    if (tid == 0)
        g_sse[blockIdx.y * 2 + blockIdx.x] = ssum[0] + ssum[1] + ssum[2] + ssum[3];
}

// ---------------- finalize --------------------------------------------------
__global__ __launch_bounds__(256) void finalize(float* __restrict__ outLoss) {
    __shared__ float sc[8];
    float k = 0.f;
    for (int i = threadIdx.x; i < NROWS; i += 256) k += g_kl[i];
    float K = blockSum(k, sc);
    float E = blockSum(g_sse[threadIdx.x], sc);
    if (threadIdx.x == 0)
        outLoss[0] = 0.25f * (E / (float)ZELEMS) + 0.01f * (K / (float)NROWS);
}

// ---------------- launch ----------------------------------------------------
extern "C" void kernel_launch(void* const* d_in, const int* in_sizes, int n_in,
                              void* d_out, int out_size) {
    const float* z  = (const float*)d_in[0];
    const float* cb = (const float*)d_in[1];
    float* out = (float*)d_out;
    float* outZ     = out;
    float* outLoss  = out + ZELEMS;
    float* outCodes = out + ZELEMS + 1;

    cudaFuncSetAttribute(gemm2, cudaFuncAttributeMaxDynamicSharedMemorySize, G2_DYN);

    split_z<<<ZELEMS / 256, 256>>>(z);
    dim3 gs(NCODES / 64, KDIM / 64);
    split_cb<<<gs, 256>>>(cb);

    dim3 g1(NCODES / 128, NROWS / 128);        // (64, 128)
    gemm1<<<g1, 128>>>();

    rowops<<<NROWS, 256>>>(outCodes);

    dim3 g2(KDIM / 128, NROWS / 128);          // (2, 128) = 256 CTAs
    gemm2<<<g2, 128, G2_DYN>>>(z, outZ);

    finalize<<<1, 256>>>(outLoss);
}

// round 16
// speedup vs baseline: 1.0785x; 1.0208x over previous
#include <cuda_runtime.h>
#include <cuda_fp16.h>
#include <stdint.h>

#define NROWS  16384
#define NCODES 8192
#define KDIM   256
#define ZELEMS (NROWS * KDIM)
#define B1 16.0f

typedef __half fp16;

__device__ float g_logits[(size_t)NROWS * NCODES];
__device__ fp16  g_Whi[(size_t)NROWS * NCODES];
__device__ fp16  g_Ahi[ZELEMS], g_Alo[ZELEMS];
__device__ fp16  g_Bhi[NCODES * KDIM], g_Blo[NCODES * KDIM];
__device__ fp16  g_CThi[(size_t)KDIM * NCODES], g_CTlo[(size_t)KDIM * NCODES];
__device__ float g_kl[NROWS];
__device__ float g_sse[256];

// ---------------- PTX helpers ----------------------------------------------
__device__ __forceinline__ uint32_t smem_u32(const void* p) {
    uint32_t a;
    asm("{ .reg .u64 t; cvta.to.shared.u64 t, %1; cvt.u32.u64 %0, t; }" : "=r"(a) : "l"(p));
    return a;
}
__device__ __forceinline__ void cp16(uint32_t dst, const void* src) {
    asm volatile("cp.async.cg.shared.global [%0], [%1], 16;\n" :: "r"(dst), "l"(src));
}
__device__ __forceinline__ void cp_commit() { asm volatile("cp.async.commit_group;\n" ::: "memory"); }
template<int N> __device__ __forceinline__ void cp_wait() {
    asm volatile("cp.async.wait_group %0;\n" :: "n"(N) : "memory");
}
__device__ __forceinline__ void ldsm4(uint32_t* r, uint32_t addr) {
    asm volatile("ldmatrix.sync.aligned.m8n8.x4.shared.b16 {%0,%1,%2,%3}, [%4];"
        : "=r"(r[0]), "=r"(r[1]), "=r"(r[2]), "=r"(r[3]) : "r"(addr));
}
__device__ __forceinline__ void mma16816(float* c, const uint32_t* a, const uint32_t* b) {
    asm volatile("mma.sync.aligned.m16n8k16.row.col.f32.f16.f16.f32 "
        "{%0,%1,%2,%3}, {%4,%5,%6,%7}, {%8,%9}, {%0,%1,%2,%3};"
        : "+f"(c[0]), "+f"(c[1]), "+f"(c[2]), "+f"(c[3])
        : "r"(a[0]), "r"(a[1]), "r"(a[2]), "r"(a[3]), "r"(b[0]), "r"(b[1]));
}

// ---------------- threefry2x32 key (0,42); G' = exp(g-24) -------------------
__device__ __forceinline__ uint2 tf2x32(uint32_t x0, uint32_t x1) {
    const uint32_t ks1 = 42u, ks2 = 0x1BD11BDAu ^ 42u;
    x1 += ks1;
#define TFR(r) { x0 += x1; x1 = (x1 << (r)) | (x1 >> (32 - (r))); x1 ^= x0; }
    TFR(13) TFR(15) TFR(26) TFR(6)
    x0 += ks1; x1 += ks2 + 1u;
    TFR(17) TFR(29) TFR(16) TFR(24)
    x0 += ks2; x1 += 2u;
    TFR(13) TFR(15) TFR(26) TFR(6)
    x1 += ks1 + 3u;
    TFR(17) TFR(29) TFR(16) TFR(24)
    x0 += ks1; x1 += ks2 + 4u;
    TFR(13) TFR(15) TFR(26) TFR(6)
    x0 += ks2; x1 += 5u;
#undef TFR
    return make_uint2(x0, x1);
}
__device__ __forceinline__ float gprime_at(uint32_t j) {
    uint2 t = tf2x32(0u, j);
    uint32_t bits = t.x ^ t.y;
    float f = __uint_as_float((bits >> 9) | 0x3f800000u) - 1.0f;
    f = fmaxf(f, 1.17549435e-38f);
    float tt = f - 1.0f;
    float inner;
    if (tt > -0.00390625f)
        inner = tt * (1.0f + tt * (-0.5f + tt * 0.33333333f));
    else
        inner = __logf(f);
    return __fdividef(3.7751345e-11f, -inner);
}

// ---------------- reductions (256 threads) ----------------------------------
__device__ __forceinline__ float blockSum(float v, float* sc) {
    int lane = threadIdx.x & 31, w = threadIdx.x >> 5;
#pragma unroll
    for (int o = 16; o; o >>= 1) v += __shfl_xor_sync(0xffffffffu, v, o);
    if (lane == 0) sc[w] = v;
    __syncthreads();
    if (w == 0) {
        float x = (lane < 8) ? sc[lane] : 0.f;
#pragma unroll
        for (int o = 4; o; o >>= 1) x += __shfl_xor_sync(0xffffffffu, x, o);
        if (lane == 0) sc[0] = x;
    }
    __syncthreads();
    float r = sc[0];
    __syncthreads();
    return r;
}
__device__ __forceinline__ void blockArgmax(float& v, int& idx, float* scv, int* sci) {
    int lane = threadIdx.x & 31, w = threadIdx.x >> 5;
#pragma unroll
    for (int o = 16; o; o >>= 1) {
        float ov = __shfl_xor_sync(0xffffffffu, v, o);
        int   oi = __shfl_xor_sync(0xffffffffu, idx, o);
        if (ov > v || (ov == v && oi < idx)) { v = ov; idx = oi; }
    }
    if (lane == 0) { scv[w] = v; sci[w] = idx; }
    __syncthreads();
    if (w == 0) {
        float x = (lane < 8) ? scv[lane] : -3.4e38f;
        int   i = (lane < 8) ? sci[lane] : 0x7fffffff;
#pragma unroll
        for (int o = 4; o; o >>= 1) {
            float ov = __shfl_xor_sync(0xffffffffu, x, o);
            int   oi = __shfl_xor_sync(0xffffffffu, i, o);
            if (ov > x || (ov == x && oi < i)) { x = ov; i = oi; }
        }
        if (lane == 0) { scv[0] = x; sci[0] = i; }
    }
    __syncthreads();
    v = scv[0]; idx = sci[0];
    __syncthreads();
}

// ---------------- merged split kernel ---------------------------------------
// grid: 16384 z-blocks + 512 cb-blocks
__global__ __launch_bounds__(256) void split_all(const float* __restrict__ z,
                                                 const float* __restrict__ cb) {
    if (blockIdx.x < 16384) {
        int i = blockIdx.x * 256 + threadIdx.x;
        float x = z[i];
        fp16 h = __float2half_rn(x);
        g_Ahi[i] = h;
        g_Alo[i] = __float2half_rn(x - __half2float(h));
        return;
    }
    __shared__ fp16 th[64][65], tl[64][65];
    int b2 = blockIdx.x - 16384;           // 0..511
    int bc = (b2 & 127) * 64;              // code tile
    int bd = (b2 >> 7) * 64;               // dim tile
    int t = threadIdx.x;
#pragma unroll 4
    for (int cc = 0; cc < 16; cc++) {
        int c = (t >> 6) * 16 + cc;
        int d = t & 63;
        size_t gi = (size_t)(bc + c) * KDIM + bd + d;
        float x = cb[gi];
        fp16 h = __float2half_rn(x);
        fp16 l = __float2half_rn(x - __half2float(h));
        g_Bhi[gi] = h; g_Blo[gi] = l;
        th[c][d] = h; tl[c][d] = l;
    }
    __syncthreads();
#pragma unroll 4
    for (int dd = 0; dd < 16; dd++) {
        int d = (t >> 6) * 16 + dd;
        int c = t & 63;
        size_t gi = (size_t)(bd + d) * NCODES + bc + c;
        g_CThi[gi] = th[c][d];
        g_CTlo[gi] = tl[c][d];
    }
}

// ---------------- gemm1: logits, 3-term, BK=64 (12 iters) -------------------
// Stage: A 128 rows x 144 B = 18432, B same; stage stride 36864; 2 stages dyn.
#define G1_RS 144u
#define G1_ARR 18432u
#define G1_STG 36864u
#define G1_DYN (2 * G1_STG)

__global__ __launch_bounds__(128) void gemm1() {
    extern __shared__ __align__(16) char dyn1[];
    uint32_t sm = smem_u32(dyn1);

    int tid = threadIdx.x, lane = tid & 31, wid = tid >> 5;
    int wm = wid >> 1, wn = wid & 1;
    int m0 = blockIdx.y * 128, n0 = blockIdx.x * 128;

    const int NIT = 12;                    // 3 terms x 4 k-chunks of 64
    const fp16* At[3] = { g_Ahi, g_Alo, g_Ahi };
    const fp16* Bt[3] = { g_Bhi, g_Bhi, g_Blo };

    float acc[4][8][4] = {};

    auto load_stage = [&](int it, int s) {
        int term = it >> 2, k0 = (it & 3) * 64;
        const fp16* A = At[term];
        const fp16* B = Bt[term];
        uint32_t base = sm + s * G1_STG;
#pragma unroll
        for (int i = 0; i < 16; i++) {
            int idx = tid + i * 128;               // 0..2047
            int arr = idx >> 10;                   // 0 = A, 1 = B
            int row = (idx >> 3) & 127;
            int ch  = idx & 7;
            const fp16* src = (arr == 0)
                ? A + (size_t)(m0 + row) * KDIM + k0 + ch * 8
                : B + (size_t)(n0 + row) * KDIM + k0 + ch * 8;
            cp16(base + arr * G1_ARR + row * G1_RS + ch * 16, src);
        }
        cp_commit();
    };

    load_stage(0, 0);
    for (int it = 0; it < NIT; it++) {
        int s = it & 1;
        cp_wait<0>();
        __syncthreads();
        if (it + 1 < NIT) load_stage(it + 1, s ^ 1);
        uint32_t da = sm + s * G1_STG;
        uint32_t db = da + G1_ARR;
#pragma unroll
        for (int ks = 0; ks < 64; ks += 16) {
            uint32_t af[4][4], bq[4][4];
#pragma unroll
            for (int mt = 0; mt < 4; mt++)
                ldsm4(af[mt], da + (uint32_t)((wm * 64 + mt * 16 + (lane & 15)) * G1_RS
                                              + (ks + ((lane >> 4) << 3)) * 2));
#pragma unroll
            for (int np = 0; np < 4; np++)
                ldsm4(bq[np], db + (uint32_t)((wn * 64 + np * 16 + (lane & 7) + ((lane >> 4) << 3)) * G1_RS
                                              + (ks + (((lane >> 3) & 1) << 3)) * 2));
#pragma unroll
            for (int mt = 0; mt < 4; mt++)
#pragma unroll
                for (int nt = 0; nt < 8; nt++)
                    mma16816(acc[mt][nt], af[mt], &bq[nt >> 1][(nt & 1) * 2]);
        }
    }

    int rbase = m0 + wm * 64 + (lane >> 2);
    int cbase = n0 + wn * 64 + (lane & 3) * 2;
#pragma unroll
    for (int mt = 0; mt < 4; mt++)
#pragma unroll
        for (int nt = 0; nt < 8; nt++) {
            int r0 = rbase + mt * 16, c0 = cbase + nt * 8;
            *(float2*)(g_logits + (size_t)r0 * NCODES + c0)       = make_float2(acc[mt][nt][0], acc[mt][nt][1]);
            *(float2*)(g_logits + (size_t)(r0 + 8) * NCODES + c0) = make_float2(acc[mt][nt][2], acc[mt][nt][3]);
        }
}

// ---------------- rowops (R13-verbatim) -------------------------------------
__global__ __launch_bounds__(256) void rowops(float* __restrict__ outCodes) {
    __shared__ float st[NCODES];
    __shared__ float scv[8];
    __shared__ int   sci[8];

    int r = blockIdx.x;
    const float* L = g_logits + (size_t)r * NCODES;

    float mx = -3.4e38f; int ai = 0;
    float se = 0.f, sel = 0.f, sy = 0.f;
    uint32_t jb = (uint32_t)r * (uint32_t)NCODES;
    for (int c = threadIdx.x; c < NCODES; c += 256) {
        float l = L[c];
        float e = __expf(l - B1);
        float t = e * gprime_at(jb + (uint32_t)c);
        st[c] = t;
        se += e; sel += e * l; sy += t;
        if (l > mx) { mx = l; ai = c; }
    }
    __syncthreads();

    blockArgmax(mx, ai, scv, sci);
    float SE  = blockSum(se, scv);
    float SEl = blockSum(sel, scv);
    float SY  = blockSum(sy, scv);

    float inv = 1.0f / SY;
    fp16* wh = g_Whi + (size_t)r * NCODES;
    for (int c = threadIdx.x; c < NCODES; c += 256) {
        wh[c] = __float2half_rn(st[c] * inv);
    }
    if (threadIdx.x == 0) {
        g_kl[r] = SEl / SE - (B1 + __logf(SE)) + 9.0109131f;   // + ln 8192
        outCodes[r] = (float)ai;
    }
}

// ---------------- gemm2 (R15-verbatim): 128x128, 2-term, 2 CTAs/SM ----------
#define G2_STG 30720u
#define G2_DYN (2 * G2_STG)

__global__ __launch_bounds__(128) void gemm2(const float* __restrict__ Z,
                                             float* __restrict__ Out) {
    extern __shared__ __align__(16) char dyn2[];
    __shared__ float ssum[4];
    uint32_t sm = smem_u32(dyn2);
    int tid = threadIdx.x, lane = tid & 31, wid = tid >> 5;
    int wm = wid >> 1, wn = wid & 1;
    int m0 = blockIdx.y * 128;
    int n0 = blockIdx.x * 128;

    float acc[4][8][4] = {};

    auto load_stage = [&](int it, int s) {
        int k0 = it * 32;
        uint32_t b = sm + s * G2_STG;
#pragma unroll
        for (int i = 0; i < 12; i++) {
            int idx = tid + i * 128;
            if (idx < 512) {
                int row = idx >> 2, ch = idx & 3;
                cp16(b + row * 80 + ch * 16, g_Whi + (size_t)(m0 + row) * NCODES + k0 + ch * 8);
            } else if (idx < 1024) {
                int j = idx - 512; int row = j >> 2, ch = j & 3;
                cp16(b + 10240 + row * 80 + ch * 16,
                     g_CThi + (size_t)(n0 + row) * NCODES + k0 + ch * 8);
            } else {
                int j = idx - 1024; int row = j >> 2, ch = j & 3;
                cp16(b + 20480 + row * 80 + ch * 16,
                     g_CTlo + (size_t)(n0 + row) * NCODES + k0 + ch * 8);
            }
        }
        cp_commit();
    };

    load_stage(0, 0);
    for (int it = 0; it < 256; it++) {
        int s = it & 1;
        cp_wait<0>();
        __syncthreads();
        if (it + 1 < 256) load_stage(it + 1, s ^ 1);
        uint32_t bh  = sm + s * G2_STG;
        uint32_t chh = bh + 10240;
        uint32_t cll = bh + 20480;
#pragma unroll
        for (int ks = 0; ks < 32; ks += 16) {
            uint32_t aoff = (uint32_t)((wm * 64 + (lane & 15)) * 80 + (ks + ((lane >> 4) << 3)) * 2);
            uint32_t boff = (uint32_t)((wn * 64 + (lane & 7) + ((lane >> 4) << 3)) * 80
                                       + (ks + (((lane >> 3) & 1) << 3)) * 2);
            uint32_t ah[4][4], bq[4][4];
#pragma unroll
            for (int mt = 0; mt < 4; mt++)
                ldsm4(ah[mt], bh + aoff + mt * 16 * 80);
#pragma unroll
            for (int np = 0; np < 4; np++)
                ldsm4(bq[np], chh + boff + np * 16 * 80);
#pragma unroll
            for (int mt = 0; mt < 4; mt++)
#pragma unroll
                for (int nt = 0; nt < 8; nt++)
                    mma16816(acc[mt][nt], ah[mt], &bq[nt >> 1][(nt & 1) * 2]);
#pragma unroll
            for (int np = 0; np < 4; np++)
                ldsm4(bq[np], cll + boff + np * 16 * 80);
#pragma unroll
            for (int mt = 0; mt < 4; mt++)
#pragma unroll
                for (int nt = 0; nt < 8; nt++)
                    mma16816(acc[mt][nt], ah[mt], &bq[nt >> 1][(nt & 1) * 2]);
        }
    }

    int rbase = m0 + wm * 64 + (lane >> 2);
    int cbase = n0 + wn * 64 + (lane & 3) * 2;
    float sse = 0.f;
#pragma unroll
    for (int mt = 0; mt < 4; mt++)
#pragma unroll
        for (int nt = 0; nt < 8; nt++) {
            int r0 = rbase + mt * 16, c0 = cbase + nt * 8;
#pragma unroll
            for (int h = 0; h < 2; h++) {
                size_t o = (size_t)(r0 + h * 8) * KDIM + c0;
                float2 zv = *(const float2*)(Z + o);
                float dx = acc[mt][nt][h * 2]     - zv.x;
                float dy = acc[mt][nt][h * 2 + 1] - zv.y;
                sse += dx * dx + dy * dy;
                *(float2*)(Out + o) = make_float2(zv.x + dx, zv.y + dy);
            }
        }
#pragma unroll
    for (int o = 16; o; o >>= 1) sse += __shfl_xor_sync(0xffffffffu, sse, o);
    if (lane == 0) ssum[wid] = sse;
    __syncthreads();
    if (tid == 0)
        g_sse[blockIdx.y * 2 + blockIdx.x] = ssum[0] + ssum[1] + ssum[2] + ssum[3];
}

// ---------------- finalize --------------------------------------------------
__global__ __launch_bounds__(256) void finalize(float* __restrict__ outLoss) {
    __shared__ float sc[8];
    float k = 0.f;
    for (int i = threadIdx.x; i < NROWS; i += 256) k += g_kl[i];
    float K = blockSum(k, sc);
    float E = blockSum(g_sse[threadIdx.x], sc);
    if (threadIdx.x == 0)
        outLoss[0] = 0.25f * (E / (float)ZELEMS) + 0.01f * (K / (float)NROWS);
}

// ---------------- launch ----------------------------------------------------
extern "C" void kernel_launch(void* const* d_in, const int* in_sizes, int n_in,
                              void* d_out, int out_size) {
    const float* z  = (const float*)d_in[0];
    const float* cb = (const float*)d_in[1];
    float* out = (float*)d_out;
    float* outZ     = out;
    float* outLoss  = out + ZELEMS;
    float* outCodes = out + ZELEMS + 1;

    cudaFuncSetAttribute(gemm1, cudaFuncAttributeMaxDynamicSharedMemorySize, G1_DYN);
    cudaFuncSetAttribute(gemm2, cudaFuncAttributeMaxDynamicSharedMemorySize, G2_DYN);

    split_all<<<16384 + 512, 256>>>(z, cb);

    dim3 g1(NCODES / 128, NROWS / 128);        // (64, 128)
    gemm1<<<g1, 128, G1_DYN>>>();

    rowops<<<NROWS, 256>>>(outCodes);

    dim3 g2(KDIM / 128, NROWS / 128);          // (2, 128)
    gemm2<<<g2, 128, G2_DYN>>>(z, outZ);

    finalize<<<1, 256>>>(outLoss);
}

// round 17
// speedup vs baseline: 1.1125x; 1.0315x over previous
#include <cuda_runtime.h>
#include <cuda_fp16.h>
#include <stdint.h>

#define NROWS  16384
#define NCODES 8192
#define KDIM   256
#define ZELEMS (NROWS * KDIM)
#define B1 16.0f

typedef __half fp16;

__device__ float g_logits[(size_t)NROWS * NCODES];
__device__ fp16  g_Whi[(size_t)NROWS * NCODES];
__device__ fp16  g_Ahi[ZELEMS], g_Alo[ZELEMS];
__device__ fp16  g_Bhi[NCODES * KDIM], g_Blo[NCODES * KDIM];
__device__ fp16  g_CThi[(size_t)KDIM * NCODES], g_CTlo[(size_t)KDIM * NCODES];
__device__ float g_kl[NROWS];
__device__ float g_sse[256];

// ---------------- PTX helpers ----------------------------------------------
__device__ __forceinline__ uint32_t smem_u32(const void* p) {
    uint32_t a;
    asm("{ .reg .u64 t; cvta.to.shared.u64 t, %1; cvt.u32.u64 %0, t; }" : "=r"(a) : "l"(p));
    return a;
}
__device__ __forceinline__ void cp16(uint32_t dst, const void* src) {
    asm volatile("cp.async.cg.shared.global [%0], [%1], 16;\n" :: "r"(dst), "l"(src));
}
__device__ __forceinline__ void cp_commit() { asm volatile("cp.async.commit_group;\n" ::: "memory"); }
template<int N> __device__ __forceinline__ void cp_wait() {
    asm volatile("cp.async.wait_group %0;\n" :: "n"(N) : "memory");
}
__device__ __forceinline__ void ldsm4(uint32_t* r, uint32_t addr) {
    asm volatile("ldmatrix.sync.aligned.m8n8.x4.shared.b16 {%0,%1,%2,%3}, [%4];"
        : "=r"(r[0]), "=r"(r[1]), "=r"(r[2]), "=r"(r[3]) : "r"(addr));
}
__device__ __forceinline__ void mma16816(float* c, const uint32_t* a, const uint32_t* b) {
    asm volatile("mma.sync.aligned.m16n8k16.row.col.f32.f16.f16.f32 "
        "{%0,%1,%2,%3}, {%4,%5,%6,%7}, {%8,%9}, {%0,%1,%2,%3};"
        : "+f"(c[0]), "+f"(c[1]), "+f"(c[2]), "+f"(c[3])
        : "r"(a[0]), "r"(a[1]), "r"(a[2]), "r"(a[3]), "r"(b[0]), "r"(b[1]));
}

// ---------------- threefry2x32 key (0,42); G' = exp(g-24) -------------------
__device__ __forceinline__ uint2 tf2x32(uint32_t x0, uint32_t x1) {
    const uint32_t ks1 = 42u, ks2 = 0x1BD11BDAu ^ 42u;
    x1 += ks1;
#define TFR(r) { x0 += x1; x1 = (x1 << (r)) | (x1 >> (32 - (r))); x1 ^= x0; }
    TFR(13) TFR(15) TFR(26) TFR(6)
    x0 += ks1; x1 += ks2 + 1u;
    TFR(17) TFR(29) TFR(16) TFR(24)
    x0 += ks2; x1 += 2u;
    TFR(13) TFR(15) TFR(26) TFR(6)
    x1 += ks1 + 3u;
    TFR(17) TFR(29) TFR(16) TFR(24)
    x0 += ks1; x1 += ks2 + 4u;
    TFR(13) TFR(15) TFR(26) TFR(6)
    x0 += ks2; x1 += 5u;
#undef TFR
    return make_uint2(x0, x1);
}
__device__ __forceinline__ float gprime_at(uint32_t j) {
    uint2 t = tf2x32(0u, j);
    uint32_t bits = t.x ^ t.y;
    float f = __uint_as_float((bits >> 9) | 0x3f800000u) - 1.0f;
    f = fmaxf(f, 1.17549435e-38f);
    float tt = f - 1.0f;
    float inner;
    if (tt > -0.00390625f)
        inner = tt * (1.0f + tt * (-0.5f + tt * 0.33333333f));
    else
        inner = __logf(f);
    return __fdividef(3.7751345e-11f, -inner);
}

// ---------------- reductions (256 threads) ----------------------------------
__device__ __forceinline__ float blockSum(float v, float* sc) {
    int lane = threadIdx.x & 31, w = threadIdx.x >> 5;
#pragma unroll
    for (int o = 16; o; o >>= 1) v += __shfl_xor_sync(0xffffffffu, v, o);
    if (lane == 0) sc[w] = v;
    __syncthreads();
    if (w == 0) {
        float x = (lane < 8) ? sc[lane] : 0.f;
#pragma unroll
        for (int o = 4; o; o >>= 1) x += __shfl_xor_sync(0xffffffffu, x, o);
        if (lane == 0) sc[0] = x;
    }
    __syncthreads();
    float r = sc[0];
    __syncthreads();
    return r;
}
__device__ __forceinline__ void blockArgmax(float& v, int& idx, float* scv, int* sci) {
    int lane = threadIdx.x & 31, w = threadIdx.x >> 5;
#pragma unroll
    for (int o = 16; o; o >>= 1) {
        float ov = __shfl_xor_sync(0xffffffffu, v, o);
        int   oi = __shfl_xor_sync(0xffffffffu, idx, o);
        if (ov > v || (ov == v && oi < idx)) { v = ov; idx = oi; }
    }
    if (lane == 0) { scv[w] = v; sci[w] = idx; }
    __syncthreads();
    if (w == 0) {
        float x = (lane < 8) ? scv[lane] : -3.4e38f;
        int   i = (lane < 8) ? sci[lane] : 0x7fffffff;
#pragma unroll
        for (int o = 4; o; o >>= 1) {
            float ov = __shfl_xor_sync(0xffffffffu, x, o);
            int   oi = __shfl_xor_sync(0xffffffffu, i, o);
            if (ov > x || (ov == x && oi < i)) { x = ov; i = oi; }
        }
        if (lane == 0) { scv[0] = x; sci[0] = i; }
    }
    __syncthreads();
    v = scv[0]; idx = sci[0];
    __syncthreads();
}

// ---------------- merged split kernel ---------------------------------------
__global__ __launch_bounds__(256) void split_all(const float* __restrict__ z,
                                                 const float* __restrict__ cb) {
    if (blockIdx.x < 16384) {
        int i = blockIdx.x * 256 + threadIdx.x;
        float x = z[i];
        fp16 h = __float2half_rn(x);
        g_Ahi[i] = h;
        g_Alo[i] = __float2half_rn(x - __half2float(h));
        return;
    }
    __shared__ fp16 th[64][65], tl[64][65];
    int b2 = blockIdx.x - 16384;
    int bc = (b2 & 127) * 64;
    int bd = (b2 >> 7) * 64;
    int t = threadIdx.x;
#pragma unroll 4
    for (int cc = 0; cc < 16; cc++) {
        int c = (t >> 6) * 16 + cc;
        int d = t & 63;
        size_t gi = (size_t)(bc + c) * KDIM + bd + d;
        float x = cb[gi];
        fp16 h = __float2half_rn(x);
        fp16 l = __float2half_rn(x - __half2float(h));
        g_Bhi[gi] = h; g_Blo[gi] = l;
        th[c][d] = h; tl[c][d] = l;
    }
    __syncthreads();
#pragma unroll 4
    for (int dd = 0; dd < 16; dd++) {
        int d = (t >> 6) * 16 + dd;
        int c = t & 63;
        size_t gi = (size_t)(bd + d) * NCODES + bc + c;
        g_CThi[gi] = th[c][d];
        g_CTlo[gi] = tl[c][d];
    }
}

// ---------------- gemm1 (R16-verbatim): logits, 3-term, BK=64 ---------------
#define G1_RS 144u
#define G1_ARR 18432u
#define G1_STG 36864u
#define G1_DYN (2 * G1_STG)

__global__ __launch_bounds__(128) void gemm1() {
    extern __shared__ __align__(16) char dyn1[];
    uint32_t sm = smem_u32(dyn1);

    int tid = threadIdx.x, lane = tid & 31, wid = tid >> 5;
    int wm = wid >> 1, wn = wid & 1;
    int m0 = blockIdx.y * 128, n0 = blockIdx.x * 128;

    const int NIT = 12;
    const fp16* At[3] = { g_Ahi, g_Alo, g_Ahi };
    const fp16* Bt[3] = { g_Bhi, g_Bhi, g_Blo };

    float acc[4][8][4] = {};

    auto load_stage = [&](int it, int s) {
        int term = it >> 2, k0 = (it & 3) * 64;
        const fp16* A = At[term];
        const fp16* B = Bt[term];
        uint32_t base = sm + s * G1_STG;
#pragma unroll
        for (int i = 0; i < 16; i++) {
            int idx = tid + i * 128;
            int arr = idx >> 10;
            int row = (idx >> 3) & 127;
            int ch  = idx & 7;
            const fp16* src = (arr == 0)
                ? A + (size_t)(m0 + row) * KDIM + k0 + ch * 8
                : B + (size_t)(n0 + row) * KDIM + k0 + ch * 8;
            cp16(base + arr * G1_ARR + row * G1_RS + ch * 16, src);
        }
        cp_commit();
    };

    load_stage(0, 0);
    for (int it = 0; it < NIT; it++) {
        int s = it & 1;
        cp_wait<0>();
        __syncthreads();
        if (it + 1 < NIT) load_stage(it + 1, s ^ 1);
        uint32_t da = sm + s * G1_STG;
        uint32_t db = da + G1_ARR;
#pragma unroll
        for (int ks = 0; ks < 64; ks += 16) {
            uint32_t af[4][4], bq[4][4];
#pragma unroll
            for (int mt = 0; mt < 4; mt++)
                ldsm4(af[mt], da + (uint32_t)((wm * 64 + mt * 16 + (lane & 15)) * G1_RS
                                              + (ks + ((lane >> 4) << 3)) * 2));
#pragma unroll
            for (int np = 0; np < 4; np++)
                ldsm4(bq[np], db + (uint32_t)((wn * 64 + np * 16 + (lane & 7) + ((lane >> 4) << 3)) * G1_RS
                                              + (ks + (((lane >> 3) & 1) << 3)) * 2));
#pragma unroll
            for (int mt = 0; mt < 4; mt++)
#pragma unroll
                for (int nt = 0; nt < 8; nt++)
                    mma16816(acc[mt][nt], af[mt], &bq[nt >> 1][(nt & 1) * 2]);
        }
    }

    int rbase = m0 + wm * 64 + (lane >> 2);
    int cbase = n0 + wn * 64 + (lane & 3) * 2;
#pragma unroll
    for (int mt = 0; mt < 4; mt++)
#pragma unroll
        for (int nt = 0; nt < 8; nt++) {
            int r0 = rbase + mt * 16, c0 = cbase + nt * 8;
            *(float2*)(g_logits + (size_t)r0 * NCODES + c0)       = make_float2(acc[mt][nt][0], acc[mt][nt][1]);
            *(float2*)(g_logits + (size_t)(r0 + 8) * NCODES + c0) = make_float2(acc[mt][nt][2], acc[mt][nt][3]);
        }
}

// ---------------- rowops (R13-verbatim) -------------------------------------
__global__ __launch_bounds__(256) void rowops(float* __restrict__ outCodes) {
    __shared__ float st[NCODES];
    __shared__ float scv[8];
    __shared__ int   sci[8];

    int r = blockIdx.x;
    const float* L = g_logits + (size_t)r * NCODES;

    float mx = -3.4e38f; int ai = 0;
    float se = 0.f, sel = 0.f, sy = 0.f;
    uint32_t jb = (uint32_t)r * (uint32_t)NCODES;
    for (int c = threadIdx.x; c < NCODES; c += 256) {
        float l = L[c];
        float e = __expf(l - B1);
        float t = e * gprime_at(jb + (uint32_t)c);
        st[c] = t;
        se += e; sel += e * l; sy += t;
        if (l > mx) { mx = l; ai = c; }
    }
    __syncthreads();

    blockArgmax(mx, ai, scv, sci);
    float SE  = blockSum(se, scv);
    float SEl = blockSum(sel, scv);
    float SY  = blockSum(sy, scv);

    float inv = 1.0f / SY;
    fp16* wh = g_Whi + (size_t)r * NCODES;
    for (int c = threadIdx.x; c < NCODES; c += 256) {
        wh[c] = __float2half_rn(st[c] * inv);
    }
    if (threadIdx.x == 0) {
        g_kl[r] = SEl / SE - (B1 + __logf(SE)) + 9.0109131f;   // + ln 8192
        outCodes[r] = (float)ai;
    }
}

// ---------------- gemm2: 128x256 tile, 256 thr, 2-term, BK=64 ---------------
// Stage: Whi 128x144 = 18432 @0, CThi 256x144 = 36864 @18432, CTlo @55296.
// Stage = 92160 B, 2 stages = 184320 B dynamic. 128 iterations.
#define G2_RS 144u
#define G2_STG 92160u
#define G2_DYN (2 * G2_STG)

__global__ __launch_bounds__(256) void gemm2(const float* __restrict__ Z,
                                             float* __restrict__ Out) {
    extern __shared__ __align__(16) char dyn2[];
    __shared__ float ssum[8];
    uint32_t sm = smem_u32(dyn2);
    int tid = threadIdx.x, lane = tid & 31, wid = tid >> 5;
    int wm = wid >> 2, wn = wid & 3;
    int m0 = blockIdx.x * 128;

    float acc[4][8][4] = {};

    auto load_stage = [&](int it, int s) {
        int k0 = it * 64;
        uint32_t b = sm + s * G2_STG;
#pragma unroll
        for (int i = 0; i < 20; i++) {
            int idx = tid + i * 256;               // 0..5119
            if (idx < 1024) {
                int row = idx >> 3, ch = idx & 7;
                cp16(b + row * G2_RS + ch * 16,
                     g_Whi + (size_t)(m0 + row) * NCODES + k0 + ch * 8);
            } else if (idx < 3072) {
                int j = idx - 1024; int row = j >> 3, ch = j & 7;
                cp16(b + 18432 + row * G2_RS + ch * 16,
                     g_CThi + (size_t)row * NCODES + k0 + ch * 8);
            } else {
                int j = idx - 3072; int row = j >> 3, ch = j & 7;
                cp16(b + 55296 + row * G2_RS + ch * 16,
                     g_CTlo + (size_t)row * NCODES + k0 + ch * 8);
            }
        }
        cp_commit();
    };

    load_stage(0, 0);
    for (int it = 0; it < 128; it++) {
        int s = it & 1;
        cp_wait<0>();
        __syncthreads();
        if (it + 1 < 128) load_stage(it + 1, s ^ 1);
        uint32_t bh  = sm + s * G2_STG;
        uint32_t chh = bh + 18432;
        uint32_t cll = bh + 55296;
#pragma unroll
        for (int ks = 0; ks < 64; ks += 16) {
            uint32_t aoff = (uint32_t)((wm * 64 + (lane & 15)) * G2_RS + (ks + ((lane >> 4) << 3)) * 2);
            uint32_t boff = (uint32_t)((wn * 64 + (lane & 7) + ((lane >> 4) << 3)) * G2_RS
                                       + (ks + (((lane >> 3) & 1) << 3)) * 2);
            uint32_t ah[4][4], bq[4][4];
#pragma unroll
            for (int mt = 0; mt < 4; mt++)
                ldsm4(ah[mt], bh + aoff + mt * 16 * G2_RS);
#pragma unroll
            for (int np = 0; np < 4; np++)
                ldsm4(bq[np], chh + boff + np * 16 * G2_RS);
#pragma unroll
            for (int mt = 0; mt < 4; mt++)
#pragma unroll
                for (int nt = 0; nt < 8; nt++)
                    mma16816(acc[mt][nt], ah[mt], &bq[nt >> 1][(nt & 1) * 2]);
#pragma unroll
            for (int np = 0; np < 4; np++)
                ldsm4(bq[np], cll + boff + np * 16 * G2_RS);
#pragma unroll
            for (int mt = 0; mt < 4; mt++)
#pragma unroll
                for (int nt = 0; nt < 8; nt++)
                    mma16816(acc[mt][nt], ah[mt], &bq[nt >> 1][(nt & 1) * 2]);
        }
    }

    int rbase = m0 + wm * 64 + (lane >> 2);
    int cbase = wn * 64 + (lane & 3) * 2;
    float sse = 0.f;
#pragma unroll
    for (int mt = 0; mt < 4; mt++)
#pragma unroll
        for (int nt = 0; nt < 8; nt++) {
            int r0 = rbase + mt * 16, c0 = cbase + nt * 8;
#pragma unroll
            for (int h = 0; h < 2; h++) {
                size_t o = (size_t)(r0 + h * 8) * KDIM + c0;
                float2 zv = *(const float2*)(Z + o);
                float dx = acc[mt][nt][h * 2]     - zv.x;
                float dy = acc[mt][nt][h * 2 + 1] - zv.y;
                sse += dx * dx + dy * dy;
                *(float2*)(Out + o) = make_float2(zv.x + dx, zv.y + dy);
            }
        }
#pragma unroll
    for (int o = 16; o; o >>= 1) sse += __shfl_xor_sync(0xffffffffu, sse, o);
    if (lane == 0) ssum[wid] = sse;
    __syncthreads();
    if (tid == 0) {
        float t = 0.f;
#pragma unroll
        for (int i = 0; i < 8; i++) t += ssum[i];
        g_sse[blockIdx.x] = t;
    }
}

// ---------------- finalize --------------------------------------------------
__global__ __launch_bounds__(256) void finalize(float* __restrict__ outLoss) {
    __shared__ float sc[8];
    float k = 0.f;
    for (int i = threadIdx.x; i < NROWS; i += 256) k += g_kl[i];
    float K = blockSum(k, sc);
    float e = (threadIdx.x < 128) ? g_sse[threadIdx.x] : 0.f;
    float E = blockSum(e, sc);
    if (threadIdx.x == 0)
        outLoss[0] = 0.25f * (E / (float)ZELEMS) + 0.01f * (K / (float)NROWS);
}

// ---------------- launch ----------------------------------------------------
extern "C" void kernel_launch(void* const* d_in, const int* in_sizes, int n_in,
                              void* d_out, int out_size) {
    const float* z  = (const float*)d_in[0];
    const float* cb = (const float*)d_in[1];
    float* out = (float*)d_out;
    float* outZ     = out;
    float* outLoss  = out + ZELEMS;
    float* outCodes = out + ZELEMS + 1;

    cudaFuncSetAttribute(gemm1, cudaFuncAttributeMaxDynamicSharedMemorySize, G1_DYN);
    cudaFuncSetAttribute(gemm2, cudaFuncAttributeMaxDynamicSharedMemorySize, G2_DYN);

    split_all<<<16384 + 512, 256>>>(z, cb);

    dim3 g1(NCODES / 128, NROWS / 128);        // (64, 128)
    gemm1<<<g1, 128, G1_DYN>>>();

    rowops<<<NROWS, 256>>>(outCodes);

    gemm2<<<NROWS / 128, 256, G2_DYN>>>(z, outZ);   // 128 CTAs

    finalize<<<1, 256>>>(outLoss);
}